// round 8
// baseline (speedup 1.0000x reference)
#include <cuda_runtime.h>

#define NN 50000
#define E_RAW 1600000
#define E_TOT (E_RAW + NN)
#define F_IN 512
#define H1N 8
#define C1N 8
#define F1 64
#define C2 40

// ---------------- scratch (static __device__ — no allocation) ----------------
__device__ int   g_src[E_TOT];
__device__ int   g_dstv[E_TOT];
__device__ int   g_csr_src[E_TOT];
__device__ int   g_deg[NN];
__device__ int   g_off[NN + 1];
__device__ int   g_cur[NN];
__device__ int   g_is64;                               // edge dtype flag
__device__ __align__(16) float g_h1[(size_t)NN * F1];  // x @ W1
__device__ __align__(16) float g_x1[(size_t)NN * F1];  // relu(layer1 out)
__device__ __align__(16) float g_as1[(size_t)NN * H1N];
__device__ __align__(16) float g_ad1[(size_t)NN * H1N];
__device__ __align__(16) float g_h2[(size_t)NN * C2];  // x1 @ W2
__device__ float g_as2[NN];
__device__ float g_ad2[NN];

// ---------------- edge dtype detection ----------------
// If edge_index is int64 (little-endian), values < 50000 mean every odd 32-bit
// word of the first entries is 0. If int32, odd words are random node ids.
__global__ void k_detect(const int* __restrict__ e32) {
    if (threadIdx.x == 0) {
        int all_zero = 1;
        #pragma unroll
        for (int i = 0; i < 32; i++)
            if (e32[2 * i + 1] != 0) all_zero = 0;
        g_is64 = all_zero;
    }
}

// ---------------- CSR build ----------------
__global__ void k_zero_deg() {
    int i = blockIdx.x * blockDim.x + threadIdx.x;
    if (i < NN) g_deg[i] = 0;
}

__device__ __forceinline__ int clampN(int v) {
    v = v < 0 ? 0 : v;
    return v >= NN ? NN - 1 : v;
}

__global__ void k_edges(const int* __restrict__ e32) {
    int i = blockIdx.x * blockDim.x + threadIdx.x;
    if (i >= E_TOT) return;
    int s, d;
    if (i < E_RAW) {
        if (g_is64) {
            s = e32[2 * (size_t)i];
            d = e32[2 * ((size_t)E_RAW + i)];
        } else {
            s = e32[i];
            d = e32[E_RAW + i];
        }
        s = clampN(s);
        d = clampN(d);
    } else {
        s = d = i - E_RAW;  // self loop
    }
    g_src[i] = s;
    g_dstv[i] = d;
    atomicAdd(&g_deg[d], 1);
}

__global__ void k_scan() {
    __shared__ int sm[1024];
    int tid = threadIdx.x;
    int carry = 0;  // same value in every thread
    for (int base = 0; base < NN; base += 1024) {
        int v = (base + tid < NN) ? g_deg[base + tid] : 0;
        sm[tid] = v;
        __syncthreads();
        #pragma unroll
        for (int off = 1; off < 1024; off <<= 1) {
            int t = (tid >= off) ? sm[tid - off] : 0;
            __syncthreads();
            sm[tid] += t;
            __syncthreads();
        }
        int excl = sm[tid] - v;
        if (base + tid < NN) {
            g_off[base + tid] = carry + excl;
            g_cur[base + tid] = carry + excl;
        }
        int tot = sm[1023];
        __syncthreads();
        carry += tot;
    }
    if (tid == 0) g_off[NN] = carry;
}

__global__ void k_fill() {
    int i = blockIdx.x * blockDim.x + threadIdx.x;
    if (i >= E_TOT) return;
    int d = g_dstv[i];
    int pos = atomicAdd(&g_cur[d], 1);
    g_csr_src[pos] = g_src[i];
}

// ---------------- GEMM (64xN tile, BK=16, 256 threads, 4x4 microtile) -------
template <int TN, int TK>
__device__ __forceinline__ void gemm_body(const float* __restrict__ A,
                                          const float* __restrict__ B,
                                          float* __restrict__ C, int M) {
    __shared__ float As[16][68];
    __shared__ float Bs[16][64];
    int tid = threadIdx.x;
    int ty = tid >> 4, tx = tid & 15;
    int m0 = blockIdx.x * 64;
    float acc[4][4] = {};
    for (int k0 = 0; k0 < TK; k0 += 16) {
        // A tile: 64 rows x 16 cols, transposed into As[k][m]
        {
            int r = tid >> 2, c4 = (tid & 3) * 4;
            float4 v = make_float4(0.f, 0.f, 0.f, 0.f);
            int m = m0 + r;
            if (m < M) v = *(const float4*)(A + (size_t)m * TK + k0 + c4);
            As[c4 + 0][r] = v.x;
            As[c4 + 1][r] = v.y;
            As[c4 + 2][r] = v.z;
            As[c4 + 3][r] = v.w;
        }
        // B tile: 16 rows x up to 64 cols
        {
            int kr = tid >> 4, n4 = (tid & 15) * 4;
            float4 v = make_float4(0.f, 0.f, 0.f, 0.f);
            if (n4 < TN) v = *(const float4*)(B + (size_t)(k0 + kr) * TN + n4);
            Bs[kr][n4 + 0] = v.x;
            Bs[kr][n4 + 1] = v.y;
            Bs[kr][n4 + 2] = v.z;
            Bs[kr][n4 + 3] = v.w;
        }
        __syncthreads();
        #pragma unroll
        for (int kk = 0; kk < 16; kk++) {
            float4 a = *(const float4*)&As[kk][ty * 4];
            float4 b = *(const float4*)&Bs[kk][tx * 4];
            float av[4] = {a.x, a.y, a.z, a.w};
            float bv[4] = {b.x, b.y, b.z, b.w};
            #pragma unroll
            for (int i = 0; i < 4; i++)
                #pragma unroll
                for (int j = 0; j < 4; j++) acc[i][j] += av[i] * bv[j];
        }
        __syncthreads();
    }
    #pragma unroll
    for (int i = 0; i < 4; i++) {
        int m = m0 + ty * 4 + i;
        if (m < M && tx * 4 < TN) {
            float4 v = make_float4(acc[i][0], acc[i][1], acc[i][2], acc[i][3]);
            *(float4*)(C + (size_t)m * TN + tx * 4) = v;
        }
    }
}

__global__ void k_gemm1(const float* __restrict__ A, const float* __restrict__ B) {
    gemm_body<F1, F_IN>(A, B, g_h1, NN);
}

__global__ void k_gemm2(const float* __restrict__ B) {
    gemm_body<C2, F1>(g_x1, B, g_h2, NN);
}

// ---------------- attention coefficients ----------------
__global__ void k_a1(const float* __restrict__ att_s, const float* __restrict__ att_d) {
    int i = blockIdx.x * blockDim.x + threadIdx.x;
    if (i >= NN * H1N) return;
    int n = i >> 3, hd = i & 7;
    const float* hp = g_h1 + (size_t)n * F1 + hd * C1N;
    float s = 0.f, d = 0.f;
    #pragma unroll
    for (int c = 0; c < C1N; c++) {
        float v = hp[c];
        s += v * att_s[hd * C1N + c];
        d += v * att_d[hd * C1N + c];
    }
    g_as1[i] = s;
    g_ad1[i] = d;
}

__global__ void k_a2(const float* __restrict__ att_s, const float* __restrict__ att_d) {
    int n = blockIdx.x * blockDim.x + threadIdx.x;
    if (n >= NN) return;
    const float* hp = g_h2 + (size_t)n * C2;
    float s = 0.f, d = 0.f;
    #pragma unroll
    for (int c = 0; c < C2; c++) {
        float v = hp[c];
        s += v * att_s[c];
        d += v * att_d[c];
    }
    g_as2[n] = s;
    g_ad2[n] = d;
}

__device__ __forceinline__ float lrelu(float e) { return e > 0.f ? e : 0.2f * e; }

// ---------------- layer 1 attention: warp per node, no atomics --------------
__global__ void k_attn1(const float* __restrict__ b1) {
    int warp = threadIdx.x >> 5, lane = threadIdx.x & 31;
    int n = blockIdx.x * 8 + warp;
    if (n >= NN) return;
    __shared__ float smx[8][8], sinv[8][8];
    int beg = g_off[n], end = g_off[n + 1];

    float adst[8];
    #pragma unroll
    for (int h = 0; h < 8; h++) adst[h] = g_ad1[(size_t)n * 8 + h];

    // phase 1: per-head max over incoming edges
    float mx[8];
    #pragma unroll
    for (int h = 0; h < 8; h++) mx[h] = -1e30f;
    for (int i = beg + lane; i < end; i += 32) {
        int s = g_csr_src[i];
        const float* ap = g_as1 + (size_t)s * 8;
        #pragma unroll
        for (int h = 0; h < 8; h++) mx[h] = fmaxf(mx[h], lrelu(ap[h] + adst[h]));
    }
    #pragma unroll
    for (int h = 0; h < 8; h++)
        #pragma unroll
        for (int o = 16; o > 0; o >>= 1)
            mx[h] = fmaxf(mx[h], __shfl_xor_sync(0xffffffffu, mx[h], o));

    // phase 2: per-head denom
    float dn[8] = {0.f, 0.f, 0.f, 0.f, 0.f, 0.f, 0.f, 0.f};
    for (int i = beg + lane; i < end; i += 32) {
        int s = g_csr_src[i];
        const float* ap = g_as1 + (size_t)s * 8;
        #pragma unroll
        for (int h = 0; h < 8; h++) dn[h] += __expf(lrelu(ap[h] + adst[h]) - mx[h]);
    }
    #pragma unroll
    for (int h = 0; h < 8; h++)
        #pragma unroll
        for (int o = 16; o > 0; o >>= 1)
            dn[h] += __shfl_xor_sync(0xffffffffu, dn[h], o);

    if (lane == 0) {
        #pragma unroll
        for (int h = 0; h < 8; h++) {
            smx[warp][h] = mx[h];
            sinv[warp][h] = 1.f / (dn[h] + 1e-16f);
        }
    }
    __syncwarp();

    // phase 3: weighted aggregation (2 channels per lane)
    int c0 = lane, c1 = lane + 32;
    int ha = lane >> 3, hb = ha + 4;
    float mxa = smx[warp][ha], mxb = smx[warp][hb];
    float iva = sinv[warp][ha], ivb = sinv[warp][hb];
    float ada = g_ad1[(size_t)n * 8 + ha], adb = g_ad1[(size_t)n * 8 + hb];
    float acc0 = 0.f, acc1 = 0.f;
    for (int i = beg; i < end; i++) {
        int s = g_csr_src[i];
        float wa = __expf(lrelu(g_as1[(size_t)s * 8 + ha] + ada) - mxa) * iva;
        float wb = __expf(lrelu(g_as1[(size_t)s * 8 + hb] + adb) - mxb) * ivb;
        acc0 += wa * g_h1[(size_t)s * F1 + c0];
        acc1 += wb * g_h1[(size_t)s * F1 + c1];
    }
    g_x1[(size_t)n * F1 + c0] = fmaxf(acc0 + b1[c0], 0.f);
    g_x1[(size_t)n * F1 + c1] = fmaxf(acc1 + b1[c1], 0.f);
}

// ---------------- layer 2 attention + log_softmax: warp per node ------------
__global__ void k_attn2(const float* __restrict__ b2, float* __restrict__ out) {
    int warp = threadIdx.x >> 5, lane = threadIdx.x & 31;
    int n = blockIdx.x * 8 + warp;
    if (n >= NN) return;
    int beg = g_off[n], end = g_off[n + 1];
    float ad = g_ad2[n];

    float mx = -1e30f;
    for (int i = beg + lane; i < end; i += 32)
        mx = fmaxf(mx, lrelu(g_as2[g_csr_src[i]] + ad));
    #pragma unroll
    for (int o = 16; o > 0; o >>= 1) mx = fmaxf(mx, __shfl_xor_sync(0xffffffffu, mx, o));

    float dn = 0.f;
    for (int i = beg + lane; i < end; i += 32)
        dn += __expf(lrelu(g_as2[g_csr_src[i]] + ad) - mx);
    #pragma unroll
    for (int o = 16; o > 0; o >>= 1) dn += __shfl_xor_sync(0xffffffffu, dn, o);
    float inv = 1.f / (dn + 1e-16f);

    float acc0 = 0.f, acc1 = 0.f;
    for (int i = beg; i < end; i++) {
        int s = g_csr_src[i];
        float w = __expf(lrelu(g_as2[s] + ad) - mx) * inv;
        acc0 += w * g_h2[(size_t)s * C2 + lane];
        if (lane < 8) acc1 += w * g_h2[(size_t)s * C2 + 32 + lane];
    }

    float v0 = acc0 + b2[lane];
    float v1r = (lane < 8) ? (acc1 + b2[32 + lane]) : -1e30f;
    float m = fmaxf(v0, v1r);
    #pragma unroll
    for (int o = 16; o > 0; o >>= 1) m = fmaxf(m, __shfl_xor_sync(0xffffffffu, m, o));
    float se = __expf(v0 - m) + ((lane < 8) ? __expf(v1r - m) : 0.f);
    #pragma unroll
    for (int o = 16; o > 0; o >>= 1) se += __shfl_xor_sync(0xffffffffu, se, o);
    float ls = m + logf(se);

    out[(size_t)n * C2 + lane] = v0 - ls;
    if (lane < 8) out[(size_t)n * C2 + 32 + lane] = v1r - ls;
}

// ---------------- launch ----------------
extern "C" void kernel_launch(void* const* d_in, const int* in_sizes, int n_in,
                              void* d_out, int out_size) {
    const float* x   = (const float*)d_in[0];
    const int*   ei  = (const int*)d_in[1];   // int32 OR int64 (auto-detected)
    const float* W1  = (const float*)d_in[2];
    const float* as1 = (const float*)d_in[3];
    const float* ad1 = (const float*)d_in[4];
    const float* b1  = (const float*)d_in[5];
    const float* W2  = (const float*)d_in[6];
    const float* as2 = (const float*)d_in[7];
    const float* ad2 = (const float*)d_in[8];
    const float* b2  = (const float*)d_in[9];
    float*       out = (float*)d_out;

    k_detect<<<1, 32>>>(ei);
    k_zero_deg<<<(NN + 255) / 256, 256>>>();
    k_edges<<<(E_TOT + 255) / 256, 256>>>(ei);
    k_scan<<<1, 1024>>>();
    k_fill<<<(E_TOT + 255) / 256, 256>>>();

    k_gemm1<<<(NN + 63) / 64, 256>>>(x, W1);
    k_a1<<<(NN * H1N + 255) / 256, 256>>>(as1, ad1);
    k_attn1<<<(NN + 7) / 8, 256>>>(b1);

    k_gemm2<<<(NN + 63) / 64, 256>>>(W2);
    k_a2<<<(NN + 255) / 256, 256>>>(as2, ad2);
    k_attn2<<<(NN + 7) / 8, 256>>>(b2, out);
}

// round 10
// speedup vs baseline: 1.3668x; 1.3668x over previous
#include <cuda_runtime.h>

#define NN 50000
#define E_RAW 1600000
#define E_TOT (E_RAW + NN)
#define F_IN 512
#define H1N 8
#define C1N 8
#define F1 64
#define C2 40
#define NB_SCAN ((NN + 255) / 256)

// ---------------- scratch (static __device__ — no allocation) ----------------
__device__ int   g_src[E_TOT];
__device__ int   g_dstv[E_TOT];
__device__ int   g_csr_src[E_TOT];
__device__ int   g_deg[NN];
__device__ int   g_off[NN + 1];
__device__ int   g_cur[NN];
__device__ int   g_bsum[NB_SCAN];
__device__ int   g_boff[NB_SCAN];
__device__ int   g_is64;                               // edge dtype flag
__device__ __align__(16) float g_h1[(size_t)NN * F1];  // x @ W1
__device__ __align__(16) float g_x1[(size_t)NN * F1];  // relu(layer1 out)
__device__ __align__(16) float g_as1[(size_t)NN * H1N];
__device__ __align__(16) float g_ad1[(size_t)NN * H1N];
__device__ __align__(16) float g_h2[(size_t)NN * C2];  // x1 @ W2
__device__ float g_as2[NN];
__device__ float g_ad2[NN];

// ---------------- edge dtype detection ----------------
__global__ void k_detect(const int* __restrict__ e32) {
    if (threadIdx.x == 0) {
        int all_zero = 1;
        #pragma unroll
        for (int i = 0; i < 32; i++)
            if (e32[2 * i + 1] != 0) all_zero = 0;
        g_is64 = all_zero;
    }
}

// ---------------- CSR build ----------------
__global__ void k_zero_deg() {
    int i = blockIdx.x * blockDim.x + threadIdx.x;
    if (i < NN) g_deg[i] = 0;
}

__device__ __forceinline__ int clampN(int v) {
    v = v < 0 ? 0 : v;
    return v >= NN ? NN - 1 : v;
}

__global__ void k_edges(const int* __restrict__ e32) {
    int i = blockIdx.x * blockDim.x + threadIdx.x;
    if (i >= E_TOT) return;
    int s, d;
    if (i < E_RAW) {
        if (g_is64) {
            const int2* e64 = (const int2*)e32;
            s = e64[i].x;
            d = e64[(size_t)E_RAW + i].x;
        } else {
            s = e32[i];
            d = e32[E_RAW + i];
        }
        s = clampN(s);
        d = clampN(d);
    } else {
        s = d = i - E_RAW;  // self loop
    }
    g_src[i] = s;
    g_dstv[i] = d;
    atomicAdd(&g_deg[d], 1);
}

// ---- multi-block exclusive scan of g_deg -> g_off, g_cur ----
__global__ void k_scan1() {
    __shared__ int sm[256];
    int tid = threadIdx.x;
    int i = blockIdx.x * 256 + tid;
    int v = (i < NN) ? g_deg[i] : 0;
    sm[tid] = v;
    __syncthreads();
    #pragma unroll
    for (int off = 1; off < 256; off <<= 1) {
        int t = (tid >= off) ? sm[tid - off] : 0;
        __syncthreads();
        sm[tid] += t;
        __syncthreads();
    }
    if (i < NN) g_off[i] = sm[tid] - v;  // local exclusive
    if (tid == 255) g_bsum[blockIdx.x] = sm[255];
}

__global__ void k_scan2() {
    __shared__ int sm[NB_SCAN];
    int tid = threadIdx.x;
    // load 196 block sums (256 threads, one pass)
    int v = (tid < NB_SCAN) ? g_bsum[tid] : 0;
    if (tid < NB_SCAN) sm[tid] = v;
    __syncthreads();
    for (int off = 1; off < NB_SCAN; off <<= 1) {
        int t = (tid >= off && tid < NB_SCAN) ? sm[tid - off] : 0;
        __syncthreads();
        if (tid < NB_SCAN) sm[tid] += t;
        __syncthreads();
    }
    if (tid < NB_SCAN) g_boff[tid] = sm[tid] - v;  // exclusive
    if (tid == 0) g_off[NN] = E_TOT;
}

__global__ void k_scan3() {
    int i = blockIdx.x * 256 + threadIdx.x;
    if (i < NN) {
        int o = g_off[i] + g_boff[blockIdx.x];
        g_off[i] = o;
        g_cur[i] = o;
    }
}

__global__ void k_fill() {
    int i = blockIdx.x * blockDim.x + threadIdx.x;
    if (i >= E_TOT) return;
    int d = g_dstv[i];
    int pos = atomicAdd(&g_cur[d], 1);
    g_csr_src[pos] = g_src[i];
}

// ---------------- GEMM (64xN tile, BK=16, 256 threads, 4x4 microtile) -------
template <int TN, int TK>
__device__ __forceinline__ void gemm_body(const float* __restrict__ A,
                                          const float* __restrict__ B,
                                          float* __restrict__ C, int M) {
    __shared__ float As[16][68];
    __shared__ float Bs[16][64];
    int tid = threadIdx.x;
    int ty = tid >> 4, tx = tid & 15;
    int m0 = blockIdx.x * 64;
    float acc[4][4] = {};
    for (int k0 = 0; k0 < TK; k0 += 16) {
        {
            int r = tid >> 2, c4 = (tid & 3) * 4;
            float4 v = make_float4(0.f, 0.f, 0.f, 0.f);
            int m = m0 + r;
            if (m < M) v = *(const float4*)(A + (size_t)m * TK + k0 + c4);
            As[c4 + 0][r] = v.x;
            As[c4 + 1][r] = v.y;
            As[c4 + 2][r] = v.z;
            As[c4 + 3][r] = v.w;
        }
        {
            int kr = tid >> 4, n4 = (tid & 15) * 4;
            float4 v = make_float4(0.f, 0.f, 0.f, 0.f);
            if (n4 < TN) v = *(const float4*)(B + (size_t)(k0 + kr) * TN + n4);
            Bs[kr][n4 + 0] = v.x;
            Bs[kr][n4 + 1] = v.y;
            Bs[kr][n4 + 2] = v.z;
            Bs[kr][n4 + 3] = v.w;
        }
        __syncthreads();
        #pragma unroll
        for (int kk = 0; kk < 16; kk++) {
            float4 a = *(const float4*)&As[kk][ty * 4];
            float4 b = *(const float4*)&Bs[kk][tx * 4];
            float av[4] = {a.x, a.y, a.z, a.w};
            float bv[4] = {b.x, b.y, b.z, b.w};
            #pragma unroll
            for (int i = 0; i < 4; i++)
                #pragma unroll
                for (int j = 0; j < 4; j++) acc[i][j] += av[i] * bv[j];
        }
        __syncthreads();
    }
    #pragma unroll
    for (int i = 0; i < 4; i++) {
        int m = m0 + ty * 4 + i;
        if (m < M && tx * 4 < TN) {
            float4 v = make_float4(acc[i][0], acc[i][1], acc[i][2], acc[i][3]);
            *(float4*)(C + (size_t)m * TN + tx * 4) = v;
        }
    }
}

__global__ void k_gemm1(const float* __restrict__ A, const float* __restrict__ B) {
    gemm_body<F1, F_IN>(A, B, g_h1, NN);
}

__global__ void k_gemm2(const float* __restrict__ B) {
    gemm_body<C2, F1>(g_x1, B, g_h2, NN);
}

// ---------------- attention coefficients ----------------
__global__ void k_a1(const float* __restrict__ att_s, const float* __restrict__ att_d) {
    int i = blockIdx.x * blockDim.x + threadIdx.x;
    if (i >= NN * H1N) return;
    int n = i >> 3, hd = i & 7;
    const float* hp = g_h1 + (size_t)n * F1 + hd * C1N;
    float s = 0.f, d = 0.f;
    #pragma unroll
    for (int c = 0; c < C1N; c++) {
        float v = hp[c];
        s += v * att_s[hd * C1N + c];
        d += v * att_d[hd * C1N + c];
    }
    g_as1[i] = s;
    g_ad1[i] = d;
}

__global__ void k_a2(const float* __restrict__ att_s, const float* __restrict__ att_d) {
    int n = blockIdx.x * blockDim.x + threadIdx.x;
    if (n >= NN) return;
    const float* hp = g_h2 + (size_t)n * C2;
    float s = 0.f, d = 0.f;
    #pragma unroll
    for (int c = 0; c < C2; c++) {
        float v = hp[c];
        s += v * att_s[c];
        d += v * att_d[c];
    }
    g_as2[n] = s;
    g_ad2[n] = d;
}

__device__ __forceinline__ float lrelu(float e) { return e > 0.f ? e : 0.2f * e; }

// -------- layer 1 attention: warp/node, SINGLE edge pass, deferred norm ------
// softmax is shift-invariant -> skip max pass; out = (sum w*h)/(sum w).
__global__ void k_attn1(const float* __restrict__ b1) {
    int warp = threadIdx.x >> 5, lane = threadIdx.x & 31;
    int n = blockIdx.x * 8 + warp;
    if (n >= NN) return;
    int beg = g_off[n], end = g_off[n + 1];

    int c0 = lane, c1 = lane + 32;
    int ha = lane >> 3, hb = ha + 4;
    float ada = g_ad1[(size_t)n * 8 + ha];
    float adb = g_ad1[(size_t)n * 8 + hb];
    float acc0 = 0.f, acc1 = 0.f, dna = 0.f, dnb = 0.f;
    for (int i = beg; i < end; i++) {
        int s = g_csr_src[i];
        float wa = __expf(lrelu(g_as1[(size_t)s * 8 + ha] + ada));
        float wb = __expf(lrelu(g_as1[(size_t)s * 8 + hb] + adb));
        acc0 += wa * g_h1[(size_t)s * F1 + c0];
        acc1 += wb * g_h1[(size_t)s * F1 + c1];
        dna += wa;
        dnb += wb;
    }
    g_x1[(size_t)n * F1 + c0] = fmaxf(acc0 / dna + b1[c0], 0.f);
    g_x1[(size_t)n * F1 + c1] = fmaxf(acc1 / dnb + b1[c1], 0.f);
}

// -------- layer 2 attention + log_softmax: warp/node, SINGLE edge pass ------
__global__ void k_attn2(const float* __restrict__ b2, float* __restrict__ out) {
    int warp = threadIdx.x >> 5, lane = threadIdx.x & 31;
    int n = blockIdx.x * 8 + warp;
    if (n >= NN) return;
    int beg = g_off[n], end = g_off[n + 1];
    float ad = g_ad2[n];

    float acc0 = 0.f, acc1 = 0.f, dn = 0.f;
    for (int i = beg; i < end; i++) {
        int s = g_csr_src[i];
        float w = __expf(lrelu(g_as2[s] + ad));
        acc0 += w * g_h2[(size_t)s * C2 + lane];
        if (lane < 8) acc1 += w * g_h2[(size_t)s * C2 + 32 + lane];
        dn += w;
    }
    float inv = 1.f / dn;

    float v0 = acc0 * inv + b2[lane];
    float v1r = (lane < 8) ? (acc1 * inv + b2[32 + lane]) : -1e30f;
    float m = fmaxf(v0, v1r);
    #pragma unroll
    for (int o = 16; o > 0; o >>= 1) m = fmaxf(m, __shfl_xor_sync(0xffffffffu, m, o));
    float se = __expf(v0 - m) + ((lane < 8) ? __expf(v1r - m) : 0.f);
    #pragma unroll
    for (int o = 16; o > 0; o >>= 1) se += __shfl_xor_sync(0xffffffffu, se, o);
    float ls = m + logf(se);

    out[(size_t)n * C2 + lane] = v0 - ls;
    if (lane < 8) out[(size_t)n * C2 + 32 + lane] = v1r - ls;
}

// ---------------- launch ----------------
extern "C" void kernel_launch(void* const* d_in, const int* in_sizes, int n_in,
                              void* d_out, int out_size) {
    const float* x   = (const float*)d_in[0];
    const int*   ei  = (const int*)d_in[1];   // int32 OR int64 (auto-detected)
    const float* W1  = (const float*)d_in[2];
    const float* as1 = (const float*)d_in[3];
    const float* ad1 = (const float*)d_in[4];
    const float* b1  = (const float*)d_in[5];
    const float* W2  = (const float*)d_in[6];
    const float* as2 = (const float*)d_in[7];
    const float* ad2 = (const float*)d_in[8];
    const float* b2  = (const float*)d_in[9];
    float*       out = (float*)d_out;

    k_detect<<<1, 32>>>(ei);
    k_zero_deg<<<(NN + 255) / 256, 256>>>();
    k_edges<<<(E_TOT + 255) / 256, 256>>>(ei);
    k_scan1<<<NB_SCAN, 256>>>();
    k_scan2<<<1, 256>>>();
    k_scan3<<<NB_SCAN, 256>>>();
    k_fill<<<(E_TOT + 255) / 256, 256>>>();

    k_gemm1<<<(NN + 63) / 64, 256>>>(x, W1);
    k_a1<<<(NN * H1N + 255) / 256, 256>>>(as1, ad1);
    k_attn1<<<(NN + 7) / 8, 256>>>(b1);

    k_gemm2<<<(NN + 63) / 64, 256>>>(W2);
    k_a2<<<(NN + 255) / 256, 256>>>(as2, ad2);
    k_attn2<<<(NN + 7) / 8, 256>>>(b2, out);
}